// round 1
// baseline (speedup 1.0000x reference)
#include <cuda_runtime.h>
#include <cstdint>

// ---------------- problem constants ----------------
#define BB 4
#define TT 2048
#define BT (BB*TT)      // 8192 tokens
#define DD 512
#define FFD 2048
#define EE 4
#define EPSV 1e-5f

// ---------------- scratch (no runtime allocation allowed) ----------------
__device__ float d_K  [BT*DD];
__device__ float d_V  [BT*DD];
__device__ float d_wv [BT*DD];
__device__ float d_pre1[BT*DD];
__device__ float d_x1 [BT*DD];
__device__ float d_ff [BT*DD];
__device__ float d_h  [BT*FFD];
__device__ float d_kvpart[8*BB*DD];
__device__ float d_kv [BB*DD];
__device__ int   d_cnt[EE];
__device__ int   d_idx[EE*BT];
__device__ float d_wgt[EE*BT];

// ---------------- generic SGEMM: 128x128 tile, BK=8, 8x8 per thread ----------------
#define BM 128
#define BN 128
#define BK 8
#define TM 8
#define TN 8

enum { M_BIAS = 0, M_BIAS_RESID = 1, M_GATHER_RELU = 2, M_SCATTER = 3 };

template <int MODE>
__global__ __launch_bounds__(256, 2)
void sgemm_kernel(const float* __restrict__ A, long long sA,
                  const float* __restrict__ Bm, long long sB,
                  float* __restrict__ C, long long sC,
                  const float* __restrict__ bias, long long sBias,
                  const float* __restrict__ resid,
                  int M, int N, int K,
                  const int* __restrict__ Mdev,
                  const int* __restrict__ gidx,
                  const float* __restrict__ gwgt)
{
    const int z = blockIdx.z;
    A += (long long)z * sA;
    Bm += (long long)z * sB;
    C += (long long)z * sC;
    bias += (long long)z * sBias;

    int Mloc = M;
    if (MODE == M_GATHER_RELU || MODE == M_SCATTER) Mloc = *Mdev;

    const int m0 = blockIdx.y * BM;
    if (m0 >= Mloc) return;
    const int n0 = blockIdx.x * BN;

    __shared__ float As[BK][BM];
    __shared__ float Bs[BK][BN];

    const int tid = threadIdx.x;
    const int aRow = tid >> 1;          // 0..127
    const int aCol = (tid & 1) * 4;     // 0 or 4
    const int bRow = tid >> 5;          // 0..7
    const int bCol = (tid & 31) * 4;    // 0..124

    const int am = m0 + aRow;
    const bool aValid = (am < Mloc);
    long long aRowG;
    if (MODE == M_GATHER_RELU) aRowG = aValid ? (long long)gidx[am] : 0;
    else aRowG = am;

    const float* Aptr = A + aRowG * (long long)K + aCol;
    const float* Bptr = Bm + (long long)bRow * N + n0 + bCol;

    const int tr = (tid >> 4) * TM;     // 0..120
    const int tc = (tid & 15) * TN;     // 0..120

    float acc[TM][TN];
    #pragma unroll
    for (int i = 0; i < TM; i++)
        #pragma unroll
        for (int j = 0; j < TN; j++) acc[i][j] = 0.f;

    for (int k0 = 0; k0 < K; k0 += BK) {
        float4 av = aValid ? *(const float4*)Aptr : make_float4(0.f, 0.f, 0.f, 0.f);
        float4 bv = *(const float4*)Bptr;
        __syncthreads();
        As[aCol + 0][aRow] = av.x;
        As[aCol + 1][aRow] = av.y;
        As[aCol + 2][aRow] = av.z;
        As[aCol + 3][aRow] = av.w;
        *(float4*)&Bs[bRow][bCol] = bv;
        __syncthreads();
        Aptr += BK;
        Bptr += (long long)BK * N;

        #pragma unroll
        for (int k = 0; k < BK; k++) {
            float ra[TM], rb[TN];
            #pragma unroll
            for (int i = 0; i < TM; i++) ra[i] = As[k][tr + i];
            #pragma unroll
            for (int j = 0; j < TN; j++) rb[j] = Bs[k][tc + j];
            #pragma unroll
            for (int i = 0; i < TM; i++)
                #pragma unroll
                for (int j = 0; j < TN; j++)
                    acc[i][j] += ra[i] * rb[j];
        }
    }

    // epilogue
    #pragma unroll
    for (int i = 0; i < TM; i++) {
        const int m = m0 + tr + i;
        if (m >= Mloc) break;
        int tok = 0; float wv = 0.f;
        if (MODE == M_SCATTER) { tok = gidx[m]; wv = gwgt[m]; }
        #pragma unroll
        for (int j = 0; j < TN; j++) {
            const int n = n0 + tc + j;
            const float v = acc[i][j] + bias[n];
            if (MODE == M_BIAS) {
                C[(long long)m * N + n] = v;
            } else if (MODE == M_BIAS_RESID) {
                C[(long long)m * N + n] = v + resid[(long long)m * N + n];
            } else if (MODE == M_GATHER_RELU) {
                C[(long long)m * N + n] = fmaxf(v, 0.f);
            } else { // M_SCATTER
                float* p = &C[(long long)tok * N + n];
                *p += wv * v;
            }
        }
    }
}

// ---------------- kv_sum: kv[b,d] = sum_t K[b,t,d]*V[b,t,d] (deterministic split) ----------------
#define TSPLIT 8
__global__ void kvsum_part_kernel(const float* __restrict__ K,
                                  const float* __restrict__ V,
                                  float* __restrict__ part)
{
    const int b = blockIdx.y;
    const int ts = blockIdx.z;
    const int d = blockIdx.x * 128 + threadIdx.x;
    const long long base = ((long long)b * TT + (long long)ts * (TT / TSPLIT)) * DD;
    const float* Kp = K + base;
    const float* Vp = V + base;
    float acc = 0.f;
    #pragma unroll 4
    for (int t = 0; t < TT / TSPLIT; t++)
        acc += Kp[(long long)t * DD + d] * Vp[(long long)t * DD + d];
    part[((long long)ts * BB + b) * DD + d] = acc;
}

__global__ void kvsum_reduce_kernel(const float* __restrict__ part, float* __restrict__ kv)
{
    const int i = blockIdx.x * blockDim.x + threadIdx.x; // < BB*DD
    float a = 0.f;
    #pragma unroll
    for (int ts = 0; ts < TSPLIT; ts++) a += part[(long long)ts * BB * DD + i];
    kv[i] = a;
}

// ---------------- LayerNorm (warp per token, D=512 -> 16 per lane) ----------------
template <bool ADD>
__global__ void ln_kernel(const float* __restrict__ a, const float* __restrict__ b,
                          const float* __restrict__ g, const float* __restrict__ beta,
                          float* __restrict__ out)
{
    const int warp = (blockIdx.x * blockDim.x + threadIdx.x) >> 5;
    const int lane = threadIdx.x & 31;
    if (warp >= BT) return;
    const float* ar = a + (long long)warp * DD;
    const float* br = ADD ? (b + (long long)warp * DD) : nullptr;
    float v[16];
    float sum = 0.f, sq = 0.f;
    #pragma unroll
    for (int i = 0; i < 16; i++) {
        const int d = i * 32 + lane;
        float x = ar[d];
        if (ADD) x += br[d];
        v[i] = x;
        sum += x;
        sq += x * x;
    }
    #pragma unroll
    for (int o = 16; o; o >>= 1) {
        sum += __shfl_xor_sync(0xffffffffu, sum, o);
        sq  += __shfl_xor_sync(0xffffffffu, sq, o);
    }
    const float mu = sum * (1.f / DD);
    const float var = sq * (1.f / DD) - mu * mu;
    const float rs = rsqrtf(var + EPSV);
    float* orow = out + (long long)warp * DD;
    #pragma unroll
    for (int i = 0; i < 16; i++) {
        const int d = i * 32 + lane;
        orow[d] = (v[i] - mu) * rs * g[d] + beta[d];
    }
}

// ---------------- gating: softmax over E=4, top-2, route ----------------
__global__ void gating_kernel(const float* __restrict__ x1,
                              const float* __restrict__ Wg,
                              const float* __restrict__ bg)
{
    const int warp = (blockIdx.x * blockDim.x + threadIdx.x) >> 5;
    const int lane = threadIdx.x & 31;
    if (warp >= BT) return;
    const float* xr = x1 + (long long)warp * DD;
    float s0 = 0.f, s1 = 0.f, s2 = 0.f, s3 = 0.f;
    for (int d = lane; d < DD; d += 32) {
        const float xv = xr[d];
        const float* w = Wg + d * EE;
        s0 += xv * w[0]; s1 += xv * w[1]; s2 += xv * w[2]; s3 += xv * w[3];
    }
    #pragma unroll
    for (int o = 16; o; o >>= 1) {
        s0 += __shfl_xor_sync(0xffffffffu, s0, o);
        s1 += __shfl_xor_sync(0xffffffffu, s1, o);
        s2 += __shfl_xor_sync(0xffffffffu, s2, o);
        s3 += __shfl_xor_sync(0xffffffffu, s3, o);
    }
    if (lane == 0) {
        float s[EE] = { s0 + bg[0], s1 + bg[1], s2 + bg[2], s3 + bg[3] };
        float mx = fmaxf(fmaxf(s[0], s[1]), fmaxf(s[2], s[3]));
        float ex[EE], sum = 0.f;
        #pragma unroll
        for (int e = 0; e < EE; e++) { ex[e] = expf(s[e] - mx); sum += ex[e]; }
        float p[EE];
        #pragma unroll
        for (int e = 0; e < EE; e++) p[e] = ex[e] / sum;
        // top-1 (ties -> lowest index, matching lax.top_k)
        int i0 = 0;
        #pragma unroll
        for (int e = 1; e < EE; e++) if (p[e] > p[i0]) i0 = e;
        int i1 = -1;
        #pragma unroll
        for (int e = 0; e < EE; e++) {
            if (e == i0) continue;
            if (i1 < 0 || p[e] > p[i1]) i1 = e;
        }
        int pos0 = atomicAdd(&d_cnt[i0], 1);
        d_idx[i0 * BT + pos0] = warp;
        d_wgt[i0 * BT + pos0] = p[i0];
        int pos1 = atomicAdd(&d_cnt[i1], 1);
        d_idx[i1 * BT + pos1] = warp;
        d_wgt[i1 * BT + pos1] = p[i1];
    }
}

// ---------------- zero ff + counts ----------------
__global__ void zero_kernel()
{
    const long long i = (long long)blockIdx.x * blockDim.x + threadIdx.x;
    if (i < (long long)BT * DD) d_ff[i] = 0.f;
    if (i < EE) d_cnt[i] = 0;
}

// ---------------- launch ----------------
extern "C" void kernel_launch(void* const* d_in, const int* in_sizes, int n_in,
                              void* d_out, int out_size)
{
    const float* x   = (const float*)d_in[0];
    const float* fb  = (const float*)d_in[1];
    const float* Wk  = (const float*)d_in[2];
    const float* bk  = (const float*)d_in[3];
    const float* Wv  = (const float*)d_in[4];
    const float* bvv = (const float*)d_in[5];
    const float* Wo  = (const float*)d_in[6];
    const float* bo  = (const float*)d_in[7];
    const float* g1  = (const float*)d_in[8];
    const float* be1 = (const float*)d_in[9];
    const float* Wg  = (const float*)d_in[10];
    const float* bg  = (const float*)d_in[11];
    const float* W1  = (const float*)d_in[12];
    const float* b1  = (const float*)d_in[13];
    const float* W2  = (const float*)d_in[14];
    const float* b2  = (const float*)d_in[15];
    const float* g2  = (const float*)d_in[16];
    const float* be2 = (const float*)d_in[17];
    float* out = (float*)d_out;

    float *K_, *V_, *wv_, *pre1_, *x1_, *ff_, *h_, *part_, *kv_, *wgt_;
    int *cnt_, *idx_;
    cudaGetSymbolAddress((void**)&K_,    d_K);
    cudaGetSymbolAddress((void**)&V_,    d_V);
    cudaGetSymbolAddress((void**)&wv_,   d_wv);
    cudaGetSymbolAddress((void**)&pre1_, d_pre1);
    cudaGetSymbolAddress((void**)&x1_,   d_x1);
    cudaGetSymbolAddress((void**)&ff_,   d_ff);
    cudaGetSymbolAddress((void**)&h_,    d_h);
    cudaGetSymbolAddress((void**)&part_, d_kvpart);
    cudaGetSymbolAddress((void**)&kv_,   d_kv);
    cudaGetSymbolAddress((void**)&cnt_,  d_cnt);
    cudaGetSymbolAddress((void**)&idx_,  d_idx);
    cudaGetSymbolAddress((void**)&wgt_,  d_wgt);

    const dim3 blk(256);

    // K = x @ Wk + bk   [8192,512] = [8192,512]x[512,512]
    sgemm_kernel<M_BIAS><<<dim3(DD/BN, BT/BM, 1), blk>>>(
        x, 0, Wk, 0, K_, 0, bk, 0, nullptr, BT, DD, DD, nullptr, nullptr, nullptr);
    // V = x @ Wv + bv
    sgemm_kernel<M_BIAS><<<dim3(DD/BN, BT/BM, 1), blk>>>(
        x, 0, Wv, 0, V_, 0, bvv, 0, nullptr, BT, DD, DD, nullptr, nullptr, nullptr);

    // kv[b,d] = sum_t K*V (deterministic split-T reduction)
    kvsum_part_kernel<<<dim3(DD/128, BB, TSPLIT), dim3(128)>>>(K_, V_, part_);
    kvsum_reduce_kernel<<<dim3((BB*DD)/256), dim3(256)>>>(part_, kv_);

    // wv[b] = fb[b] @ V[b] + kv[b]  (batched over z, bias stride D per batch)
    sgemm_kernel<M_BIAS><<<dim3(DD/BN, TT/BM, BB), blk>>>(
        fb, (long long)TT*TT, V_, (long long)TT*DD, wv_, (long long)TT*DD,
        kv_, DD, nullptr, TT, DD, TT, nullptr, nullptr, nullptr);

    // pre1 = x + wv @ Wo + bo
    sgemm_kernel<M_BIAS_RESID><<<dim3(DD/BN, BT/BM, 1), blk>>>(
        wv_, 0, Wo, 0, pre1_, 0, bo, 0, x, BT, DD, DD, nullptr, nullptr, nullptr);

    // x1 = LN(pre1)
    ln_kernel<false><<<dim3(BT/8), dim3(256)>>>(pre1_, nullptr, g1, be1, x1_);

    // zero ff + routing counts
    zero_kernel<<<dim3((BT*DD + 255)/256), dim3(256)>>>();

    // gating + routing
    gating_kernel<<<dim3(BT/8), dim3(256)>>>(x1_, Wg, bg);

    // MoE experts (top-2 routed): h = relu(gather(x1) @ W1e + b1e); ff += w * (h @ W2e + b2e)
    for (int e = 0; e < EE; e++) {
        sgemm_kernel<M_GATHER_RELU><<<dim3(FFD/BN, BT/BM, 1), blk>>>(
            x1_, 0, W1 + (long long)e*DD*FFD, 0, h_, 0, b1 + (long long)e*FFD, 0,
            nullptr, BT, FFD, DD, cnt_ + e, idx_ + e*BT, nullptr);
        sgemm_kernel<M_SCATTER><<<dim3(DD/BN, BT/BM, 1), blk>>>(
            h_, 0, W2 + (long long)e*FFD*DD, 0, ff_, 0, b2 + (long long)e*DD, 0,
            nullptr, BT, DD, FFD, cnt_ + e, idx_ + e*BT, wgt_ + e*BT);
    }

    // out = LN(x1 + ff)
    ln_kernel<true><<<dim3(BT/8), dim3(256)>>>(x1_, ff_, g2, be2, out);
}

// round 7
// speedup vs baseline: 1.3824x; 1.3824x over previous
#include <cuda_runtime.h>
#include <cstdint>

// ---------------- problem constants ----------------
#define BBATCH 4
#define TT 2048
#define BTOK 8192        // B*T tokens
#define DD 512
#define FFD 2048
#define EE 4
#define EPSV 1e-5f

// ---------------- scratch (static device memory; no runtime allocation) -------
__device__ float d_K   [BTOK*DD];
__device__ float d_V   [BTOK*DD];
__device__ float d_wv  [BTOK*DD];
__device__ float d_pre1[BTOK*DD];
__device__ float d_x1  [BTOK*DD];
__device__ float d_h   [EE*BTOK*FFD];
__device__ float d_y   [EE*BTOK*DD];
__device__ float d_kvpart[8*BBATCH*DD];
__device__ float d_kv  [BBATCH*DD];
__device__ int   d_cnt [EE];
__device__ int   d_tok [EE*BTOK];
__device__ int   d_goff[2*BTOK];
__device__ float d_gw  [2*BTOK];

// ---------------- tf32 helpers (base ISA, works on compute_103) ----------------
__device__ __forceinline__ uint32_t f2tf(float x) {
    uint32_t r;
    asm("cvt.rna.tf32.f32 %0, %1;" : "=r"(r) : "f"(x));
    return r;
}
__device__ __forceinline__ void mma_tf32(float* c, const uint32_t* a, const uint32_t* b) {
    asm volatile(
        "mma.sync.aligned.m16n8k8.row.col.f32.tf32.tf32.f32 "
        "{%0,%1,%2,%3}, {%4,%5,%6,%7}, {%8,%9}, {%0,%1,%2,%3};"
        : "+f"(c[0]), "+f"(c[1]), "+f"(c[2]), "+f"(c[3])
        : "r"(a[0]), "r"(a[1]), "r"(a[2]), "r"(a[3]), "r"(b[0]), "r"(b[1]));
}

// ---------------- tensor GEMM: 128x128 tile, BK=32, mma.sync tf32 --------------
// 256 threads = 8 warps in 2(m) x 4(n); warp tile 64x32 = 4x4 m16n8 frags.
// smem holds fragment-permuted tiles: A-frag = 1 LDS.128, B-frag = 1 LDS.64.
#define SMEM_SZ (65536)

enum { M_BIAS = 0, M_BIAS_RESID = 1, M_GATHER_RELU = 2, M_DYN = 3 };

template <int MODE>
__global__ void __launch_bounds__(256)
tc_gemm(const float* __restrict__ A, long long sAz,
        const float* __restrict__ Bm, int ldb, long long sBz,
        float* __restrict__ C, int ldc, long long sCz,
        const float* __restrict__ bias, long long sbz,
        const float* __restrict__ resid,
        int M, int K,
        const int* __restrict__ Mdev, const int* __restrict__ gidxBase)
{
    const int z = blockIdx.z;
    int Mloc = M;
    if (MODE == M_GATHER_RELU || MODE == M_DYN) Mloc = Mdev[z];
    const int m0 = blockIdx.y * 128;
    if (m0 >= Mloc) return;
    const int n0 = blockIdx.x * 128;

    A += z * sAz; Bm += z * sBz; C += z * sCz; bias += z * sbz;
    const int* gidx = (MODE == M_GATHER_RELU) ? gidxBase + z * BTOK : nullptr;

    extern __shared__ uint32_t smem[];
    uint32_t* As = smem;            // [2][4096]  (16KB per stage)
    uint32_t* Bs = smem + 8192;     // [2][4096]

    const int tid = threadIdx.x, wid = tid >> 5, lane = tid & 31;

    // ---- per-thread load descriptors (fixed across K-stages) ----
    const float* ap[4]; int aoff[4];
    const float* bp[4]; int boff[4];
    #pragma unroll
    for (int i = 0; i < 4; i++) {
        const int idx = i * 256 + tid;
        // A: 128 rows x 8 float4-cols
        const int r = idx >> 3, c4 = idx & 7;
        int m = m0 + r; if (m > Mloc - 1) m = Mloc - 1;
        const long long g = (MODE == M_GATHER_RELU) ? (long long)gidx[m] : (long long)m;
        ap[i] = A + g * (long long)K + c4 * 4;
        aoff[i] = ((c4 >> 1) * 8 + (r >> 4)) * 128 + (r & 7) * 16
                + ((r >> 3) & 1) + 2 * (c4 & 1);
        // B: 32 k-rows x 32 float4-cols
        const int kr = idx >> 5, n4 = idx & 31;
        bp[i] = Bm + (long long)kr * ldb + n0 + n4 * 4;
        boff[i] = ((kr >> 3) * 16 + (n4 >> 1)) * 64 + (n4 & 1) * 32
                + (kr & 3) * 2 + ((kr >> 2) & 1);
    }

    float acc[4][4][4];
    #pragma unroll
    for (int mi = 0; mi < 4; mi++)
        #pragma unroll
        for (int nj = 0; nj < 4; nj++)
            #pragma unroll
            for (int e = 0; e < 4; e++) acc[mi][nj][e] = 0.f;

    const int S = K / 32;
    const int mtb = (wid >> 2) * 4, ntb = (wid & 3) * 4;
    float4 arg[4], brg[4];

    auto ldg_stage = [&]() {
        #pragma unroll
        for (int i = 0; i < 4; i++) {
            arg[i] = *(const float4*)ap[i]; ap[i] += 32;
            brg[i] = *(const float4*)bp[i]; bp[i] += (long long)32 * ldb;
        }
    };
    auto sts_stage = [&](int buf) {
        uint32_t* A_ = As + buf * 4096;
        uint32_t* B_ = Bs + buf * 4096;
        #pragma unroll
        for (int i = 0; i < 4; i++) {
            uint32_t* pa = A_ + aoff[i];
            pa[0]  = f2tf(arg[i].x); pa[4]  = f2tf(arg[i].y);
            pa[8]  = f2tf(arg[i].z); pa[12] = f2tf(arg[i].w);
            uint32_t* pb = B_ + boff[i];
            pb[0]  = f2tf(brg[i].x); pb[8]  = f2tf(brg[i].y);
            pb[16] = f2tf(brg[i].z); pb[24] = f2tf(brg[i].w);
        }
    };
    auto compute_stage = [&](int buf) {
        const uint32_t* A_ = As + buf * 4096;
        const uint32_t* B_ = Bs + buf * 4096;
        #pragma unroll
        for (int k8 = 0; k8 < 4; k8++) {
            uint4 af[4]; uint2 bf[4];
            #pragma unroll
            for (int mi = 0; mi < 4; mi++)
                af[mi] = *(const uint4*)(A_ + ((k8 * 8 + mtb + mi) * 32 + lane) * 4);
            #pragma unroll
            for (int nj = 0; nj < 4; nj++)
                bf[nj] = *(const uint2*)(B_ + ((k8 * 16 + ntb + nj) * 32 + lane) * 2);
            #pragma unroll
            for (int mi = 0; mi < 4; mi++)
                #pragma unroll
                for (int nj = 0; nj < 4; nj++)
                    mma_tf32(acc[mi][nj], (const uint32_t*)&af[mi], (const uint32_t*)&bf[nj]);
        }
    };

    ldg_stage();
    sts_stage(0);
    __syncthreads();

    for (int s = 0; s < S; s++) {
        if (s + 1 < S) ldg_stage();
        compute_stage(s & 1);
        if (s + 1 < S) {
            sts_stage((s + 1) & 1);
            __syncthreads();
        }
    }

    // ---- epilogue ----
    const int rbase = m0 + (wid >> 2) * 64 + (lane >> 2);
    const int cbase = n0 + (wid & 3) * 32 + 2 * (lane & 3);
    #pragma unroll
    for (int mi = 0; mi < 4; mi++) {
        #pragma unroll
        for (int h2 = 0; h2 < 2; h2++) {
            const int m = rbase + mi * 16 + h2 * 8;
            if (m >= Mloc) continue;
            float* crow = C + (long long)m * ldc;
            const float* rrow = (MODE == M_BIAS_RESID) ? (resid + (long long)m * ldc) : nullptr;
            #pragma unroll
            for (int nj = 0; nj < 4; nj++) {
                const int n = cbase + nj * 8;
                float v0 = acc[mi][nj][h2 * 2 + 0] + bias[n];
                float v1 = acc[mi][nj][h2 * 2 + 1] + bias[n + 1];
                if (MODE == M_GATHER_RELU) { v0 = fmaxf(v0, 0.f); v1 = fmaxf(v1, 0.f); }
                if (MODE == M_BIAS_RESID) { v0 += rrow[n]; v1 += rrow[n + 1]; }
                float2 vv; vv.x = v0; vv.y = v1;
                *(float2*)(crow + n) = vv;
            }
        }
    }
}

// ---------------- kv_sum: kv[b,d] = sum_t K[b,t,d]*V[b,t,d] ----------------
#define TSPLIT 8
__global__ void kvsum_part_kernel(const float* __restrict__ K,
                                  const float* __restrict__ V,
                                  float* __restrict__ part)
{
    const int b = blockIdx.y, ts = blockIdx.z;
    const int d = blockIdx.x * 128 + threadIdx.x;
    const long long base = ((long long)b * TT + (long long)ts * (TT / TSPLIT)) * DD;
    const float* Kp = K + base;
    const float* Vp = V + base;
    float acc = 0.f;
    #pragma unroll 4
    for (int t = 0; t < TT / TSPLIT; t++)
        acc += Kp[(long long)t * DD + d] * Vp[(long long)t * DD + d];
    part[((long long)ts * BBATCH + b) * DD + d] = acc;
}
__global__ void kvsum_reduce_kernel(const float* __restrict__ part, float* __restrict__ kv)
{
    const int i = blockIdx.x * blockDim.x + threadIdx.x;
    float a = 0.f;
    #pragma unroll
    for (int ts = 0; ts < TSPLIT; ts++) a += part[(long long)ts * BBATCH * DD + i];
    kv[i] = a;
}

// ---------------- LayerNorm (warp/token) ----------------
__global__ void ln1_kernel(const float* __restrict__ a,
                           const float* __restrict__ g, const float* __restrict__ beta,
                           float* __restrict__ out)
{
    const int t = (blockIdx.x * blockDim.x + threadIdx.x) >> 5;
    const int lane = threadIdx.x & 31;
    if (t >= BTOK) return;
    const float* ar = a + (long long)t * DD;
    float v[16], sum = 0.f, sq = 0.f;
    #pragma unroll
    for (int i = 0; i < 16; i++) {
        const float x = ar[i * 32 + lane];
        v[i] = x; sum += x; sq += x * x;
    }
    #pragma unroll
    for (int o = 16; o; o >>= 1) {
        sum += __shfl_xor_sync(0xffffffffu, sum, o);
        sq  += __shfl_xor_sync(0xffffffffu, sq, o);
    }
    const float mu = sum * (1.f / DD);
    const float rs = rsqrtf(sq * (1.f / DD) - mu * mu + EPSV);
    float* orow = out + (long long)t * DD;
    #pragma unroll
    for (int i = 0; i < 16; i++) {
        const int d = i * 32 + lane;
        orow[d] = (v[i] - mu) * rs * g[d] + beta[d];
    }
}

// final LN: out = LN(x1 + w0*y[off0] + w1*y[off1])
__global__ void ln2_moe_kernel(const float* __restrict__ x1, const float* __restrict__ y,
                               const int* __restrict__ goff, const float* __restrict__ gw,
                               const float* __restrict__ g, const float* __restrict__ beta,
                               float* __restrict__ out)
{
    const int t = (blockIdx.x * blockDim.x + threadIdx.x) >> 5;
    const int lane = threadIdx.x & 31;
    if (t >= BTOK) return;
    const float* ar = x1 + (long long)t * DD;
    const float* y0 = y + (long long)goff[2 * t] * DD;
    const float* y1 = y + (long long)goff[2 * t + 1] * DD;
    const float w0 = gw[2 * t], w1 = gw[2 * t + 1];
    float v[16], sum = 0.f, sq = 0.f;
    #pragma unroll
    for (int i = 0; i < 16; i++) {
        const int d = i * 32 + lane;
        const float x = ar[d] + w0 * y0[d] + w1 * y1[d];
        v[i] = x; sum += x; sq += x * x;
    }
    #pragma unroll
    for (int o = 16; o; o >>= 1) {
        sum += __shfl_xor_sync(0xffffffffu, sum, o);
        sq  += __shfl_xor_sync(0xffffffffu, sq, o);
    }
    const float mu = sum * (1.f / DD);
    const float rs = rsqrtf(sq * (1.f / DD) - mu * mu + EPSV);
    float* orow = out + (long long)t * DD;
    #pragma unroll
    for (int i = 0; i < 16; i++) {
        const int d = i * 32 + lane;
        orow[d] = (v[i] - mu) * rs * g[d] + beta[d];
    }
}

// ---------------- gating: softmax(E=4), top-2, route ----------------
__global__ void gating_kernel(const float* __restrict__ x1,
                              const float* __restrict__ Wg,
                              const float* __restrict__ bg)
{
    const int t = (blockIdx.x * blockDim.x + threadIdx.x) >> 5;
    const int lane = threadIdx.x & 31;
    if (t >= BTOK) return;
    const float* xr = x1 + (long long)t * DD;
    float s0 = 0.f, s1 = 0.f, s2 = 0.f, s3 = 0.f;
    for (int d = lane; d < DD; d += 32) {
        const float xv = xr[d];
        const float* w = Wg + d * EE;
        s0 += xv * w[0]; s1 += xv * w[1]; s2 += xv * w[2]; s3 += xv * w[3];
    }
    #pragma unroll
    for (int o = 16; o; o >>= 1) {
        s0 += __shfl_xor_sync(0xffffffffu, s0, o);
        s1 += __shfl_xor_sync(0xffffffffu, s1, o);
        s2 += __shfl_xor_sync(0xffffffffu, s2, o);
        s3 += __shfl_xor_sync(0xffffffffu, s3, o);
    }
    if (lane == 0) {
        float s[EE] = { s0 + bg[0], s1 + bg[1], s2 + bg[2], s3 + bg[3] };
        const float mx = fmaxf(fmaxf(s[0], s[1]), fmaxf(s[2], s[3]));
        float ex[EE], sm = 0.f;
        #pragma unroll
        for (int e = 0; e < EE; e++) { ex[e] = expf(s[e] - mx); sm += ex[e]; }
        float p[EE];
        #pragma unroll
        for (int e = 0; e < EE; e++) p[e] = ex[e] / sm;
        int i0 = 0;
        #pragma unroll
        for (int e = 1; e < EE; e++) if (p[e] > p[i0]) i0 = e;
        int i1 = -1;
        #pragma unroll
        for (int e = 0; e < EE; e++) {
            if (e == i0) continue;
            if (i1 < 0 || p[e] > p[i1]) i1 = e;
        }
        const int pos0 = atomicAdd(&d_cnt[i0], 1);
        d_tok[i0 * BTOK + pos0] = t;
        d_goff[2 * t] = i0 * BTOK + pos0;
        d_gw[2 * t] = p[i0];
        const int pos1 = atomicAdd(&d_cnt[i1], 1);
        d_tok[i1 * BTOK + pos1] = t;
        d_goff[2 * t + 1] = i1 * BTOK + pos1;
        d_gw[2 * t + 1] = p[i1];
    }
}

__global__ void zero_cnt_kernel()
{
    if (threadIdx.x < EE) d_cnt[threadIdx.x] = 0;
}

// ---------------- launch ----------------
extern "C" void kernel_launch(void* const* d_in, const int* in_sizes, int n_in,
                              void* d_out, int out_size)
{
    const float* x   = (const float*)d_in[0];
    const float* fb  = (const float*)d_in[1];
    const float* Wk  = (const float*)d_in[2];
    const float* bk  = (const float*)d_in[3];
    const float* Wv  = (const float*)d_in[4];
    const float* bvv = (const float*)d_in[5];
    const float* Wo  = (const float*)d_in[6];
    const float* bo  = (const float*)d_in[7];
    const float* g1  = (const float*)d_in[8];
    const float* be1 = (const float*)d_in[9];
    const float* Wg  = (const float*)d_in[10];
    const float* bg  = (const float*)d_in[11];
    const float* W1  = (const float*)d_in[12];
    const float* b1  = (const float*)d_in[13];
    const float* W2  = (const float*)d_in[14];
    const float* b2  = (const float*)d_in[15];
    const float* g2  = (const float*)d_in[16];
    const float* be2 = (const float*)d_in[17];
    float* out = (float*)d_out;

    float *K_, *V_, *wv_, *pre1_, *x1_, *h_, *y_, *part_, *kv_, *gw_;
    int *cnt_, *tok_, *goff_;
    cudaGetSymbolAddress((void**)&K_,    d_K);
    cudaGetSymbolAddress((void**)&V_,    d_V);
    cudaGetSymbolAddress((void**)&wv_,   d_wv);
    cudaGetSymbolAddress((void**)&pre1_, d_pre1);
    cudaGetSymbolAddress((void**)&x1_,   d_x1);
    cudaGetSymbolAddress((void**)&h_,    d_h);
    cudaGetSymbolAddress((void**)&y_,    d_y);
    cudaGetSymbolAddress((void**)&part_, d_kvpart);
    cudaGetSymbolAddress((void**)&kv_,   d_kv);
    cudaGetSymbolAddress((void**)&cnt_,  d_cnt);
    cudaGetSymbolAddress((void**)&tok_,  d_tok);
    cudaGetSymbolAddress((void**)&goff_, d_goff);
    cudaGetSymbolAddress((void**)&gw_,   d_gw);

    cudaFuncSetAttribute(tc_gemm<M_BIAS>,        cudaFuncAttributeMaxDynamicSharedMemorySize, SMEM_SZ);
    cudaFuncSetAttribute(tc_gemm<M_BIAS_RESID>,  cudaFuncAttributeMaxDynamicSharedMemorySize, SMEM_SZ);
    cudaFuncSetAttribute(tc_gemm<M_GATHER_RELU>, cudaFuncAttributeMaxDynamicSharedMemorySize, SMEM_SZ);
    cudaFuncSetAttribute(tc_gemm<M_DYN>,         cudaFuncAttributeMaxDynamicSharedMemorySize, SMEM_SZ);

    zero_cnt_kernel<<<1, 32>>>();

    // K = x @ Wk + bk ; V = x @ Wv + bv
    tc_gemm<M_BIAS><<<dim3(DD/128, BTOK/128, 1), 256, SMEM_SZ>>>(
        x, 0, Wk, DD, 0, K_, DD, 0, bk, 0, nullptr, BTOK, DD, nullptr, nullptr);
    tc_gemm<M_BIAS><<<dim3(DD/128, BTOK/128, 1), 256, SMEM_SZ>>>(
        x, 0, Wv, DD, 0, V_, DD, 0, bvv, 0, nullptr, BTOK, DD, nullptr, nullptr);

    // kv[b,d] = sum_t K*V
    kvsum_part_kernel<<<dim3(DD/128, BBATCH, TSPLIT), 128>>>(K_, V_, part_);
    kvsum_reduce_kernel<<<dim3((BBATCH*DD)/256), 256>>>(part_, kv_);

    // wv[b] = fb[b] @ V[b] + kv[b]
    tc_gemm<M_BIAS><<<dim3(DD/128, TT/128, BBATCH), 256, SMEM_SZ>>>(
        fb, (long long)TT*TT, V_, DD, (long long)TT*DD, wv_, DD, (long long)TT*DD,
        kv_, DD, nullptr, TT, TT, nullptr, nullptr);

    // pre1 = x + wv @ Wo + bo
    tc_gemm<M_BIAS_RESID><<<dim3(DD/128, BTOK/128, 1), 256, SMEM_SZ>>>(
        wv_, 0, Wo, DD, 0, pre1_, DD, 0, bo, 0, x, BTOK, DD, nullptr, nullptr);

    // x1 = LN(pre1)
    ln1_kernel<<<BTOK/8, 256>>>(pre1_, g1, be1, x1_);

    // gating + routing
    gating_kernel<<<BTOK/8, 256>>>(x1_, Wg, bg);

    // MoE experts, all 4 batched on z:
    // h[e] = relu(gather(x1) @ W1[e] + b1[e])
    tc_gemm<M_GATHER_RELU><<<dim3(FFD/128, BTOK/128, EE), 256, SMEM_SZ>>>(
        x1_, 0, W1, FFD, (long long)DD*FFD, h_, FFD, (long long)BTOK*FFD,
        b1, FFD, nullptr, 0, DD, cnt_, tok_);
    // y[e] = h[e] @ W2[e] + b2[e]
    tc_gemm<M_DYN><<<dim3(DD/128, BTOK/128, EE), 256, SMEM_SZ>>>(
        h_, (long long)BTOK*FFD, W2, DD, (long long)FFD*DD, y_, DD, (long long)BTOK*DD,
        b2, DD, nullptr, 0, FFD, cnt_, nullptr);

    // out = LN(x1 + w0*y[off0] + w1*y[off1])
    ln2_moe_kernel<<<BTOK/8, 256>>>(x1_, y_, goff_, gw_, g2, be2, out);
}

// round 10
// speedup vs baseline: 3.1635x; 2.2884x over previous
#include <cuda_runtime.h>
#include <cuda_bf16.h>
#include <cstdint>

// ---------------- problem constants ----------------
#define BBATCH 4
#define TT 2048
#define BTOK 8192        // B*T tokens
#define DD 512
#define FFD 2048
#define EE 4
#define EPSV 1e-5f

// ---------------- scratch (static device memory; no runtime allocation) -------
__device__ float d_K   [BTOK*DD];
__device__ float d_V   [BTOK*DD];
__device__ float d_wv  [BTOK*DD];
__device__ float d_pre1[BTOK*DD];
__device__ float d_x1  [BTOK*DD];
__device__ float d_h   [EE*BTOK*FFD];
__device__ float d_y   [EE*BTOK*DD];
__device__ float d_kvpart[8*BBATCH*DD];
__device__ float d_kv  [BBATCH*DD];
__device__ int   d_cnt [EE];
__device__ int   d_tok [EE*BTOK];
__device__ int   d_goff[2*BTOK];
__device__ float d_gw  [2*BTOK];

// ---------------- bf16 split helpers ----------------
__device__ __forceinline__ uint32_t bfpack(float lo, float hi) {
    uint32_t r;
    asm("cvt.rn.bf16x2.f32 %0, %1, %2;" : "=r"(r) : "f"(hi), "f"(lo));
    return r;
}
__device__ __forceinline__ float bflowf(uint32_t w)  { return __uint_as_float(w << 16); }
__device__ __forceinline__ float bfhighf(uint32_t w) { return __uint_as_float(w & 0xffff0000u); }

__device__ __forceinline__ void mma_bf(float* c, const uint4& a, const uint2& b) {
    asm volatile(
        "mma.sync.aligned.m16n8k16.row.col.f32.bf16.bf16.f32 "
        "{%0,%1,%2,%3}, {%4,%5,%6,%7}, {%8,%9}, {%0,%1,%2,%3};"
        : "+f"(c[0]), "+f"(c[1]), "+f"(c[2]), "+f"(c[3])
        : "r"(a.x), "r"(a.y), "r"(a.z), "r"(a.w), "r"(b.x), "r"(b.y));
}

// ---------------- tensor GEMM: 128x128 tile, BK=32, bf16-split (3 products) ----
// 128 threads = 4 warps (2m x 2n), warp tile 64x64 = 4x8 m16n8 frags.
// smem per stage (words): Ahi[2048] Alo[2048] Bhi[2048] Blo[2048]; 2 stages = 64KB.
#define SMEM_SZ 65536

enum { M_BIAS = 0, M_BIAS_RESID = 1, M_GATHER_RELU = 2, M_DYN = 3 };

template <int MODE>
__global__ void __launch_bounds__(128, 2)
tc_gemm(const float* __restrict__ A, long long sAz,
        const float* __restrict__ Bm, int ldb, long long sBz,
        float* __restrict__ C, int ldc, long long sCz,
        const float* __restrict__ bias, long long sbz,
        const float* __restrict__ resid,
        int M, int K,
        const int* __restrict__ Mdev, const int* __restrict__ gidxBase)
{
    const int z = blockIdx.z;
    int Mloc = M;
    if (MODE == M_GATHER_RELU || MODE == M_DYN) Mloc = Mdev[z];
    const int m0 = blockIdx.y * 128;
    if (m0 >= Mloc) return;
    const int n0 = blockIdx.x * 128;

    A += z * sAz; Bm += z * sBz; C += z * sCz; bias += z * sbz;
    const int* gidx = (MODE == M_GATHER_RELU) ? gidxBase + z * BTOK : nullptr;

    extern __shared__ uint32_t smem[];
    const int tid = threadIdx.x, wid = tid >> 5, lane = tid & 31;
    const int mtb = (wid >> 1) * 4;   // mrow-unit base (16-row frags)
    const int ntb = (wid & 1) * 8;    // ncol-unit base (8-col frags)

    // ---- A fill descriptors: thread owns c4 = tid&7, rows r = i*16 + r0 ----
    const int c4 = tid & 7, r0 = tid >> 3;
    const float* aptr[8];
    #pragma unroll
    for (int i = 0; i < 8; i++) {
        int m = m0 + i * 16 + r0; if (m > Mloc - 1) m = Mloc - 1;
        const long long g = (MODE == M_GATHER_RELU) ? (long long)gidx[m] : (long long)m;
        aptr[i] = A + g * (long long)K + c4 * 4;
    }
    int aC[2];
    #pragma unroll
    for (int p = 0; p < 2; p++) {
        const int t = 2 * c4 + p;
        const int kk = t >> 3, tig = t & 3, cbit = (t >> 2) & 1;
        const int gg = r0 & 7, rbit = (r0 >> 3) & 1;
        const int slot = ((gg << 2) | tig) ^ kk;
        aC[p] = kk * 1024 + slot * 4 + rbit + 2 * cbit;
    }
    // ---- B fill descriptors: slot i -> (kk = i>>2, tig = i&3), n = tid ----
    const float* bbase = Bm + n0 + tid;
    int bOff[8];
    #pragma unroll
    for (int i = 0; i < 8; i++) {
        const int kk = i >> 2, tig = i & 3;
        const int ncol = tid >> 3, gg = tid & 7;
        const int slot = ((gg << 2) | tig) ^ (((gg >> 2) & 1) << 2);
        bOff[i] = ((kk * 16 + ncol) * 32 + slot) * 2;
    }

    float acc[4][8][4];
    #pragma unroll
    for (int mi = 0; mi < 4; mi++)
        #pragma unroll
        for (int nj = 0; nj < 8; nj++)
            #pragma unroll
            for (int e = 0; e < 4; e++) acc[mi][nj][e] = 0.f;

    const int S = K / 32;
    float4 arg[8];
    float  brg[8][4];

    auto ldgA = [&]() {
        #pragma unroll
        for (int i = 0; i < 8; i++) { arg[i] = *(const float4*)aptr[i]; aptr[i] += 32; }
    };
    auto ldgB = [&]() {
        #pragma unroll
        for (int i = 0; i < 8; i++) {
            const int kb = (i >> 2) * 16 + 2 * (i & 3);
            const float* p = bbase + (long long)kb * ldb;
            brg[i][0] = p[0];
            brg[i][1] = p[ldb];
            brg[i][2] = p[8 * ldb];
            brg[i][3] = p[9 * ldb];
        }
        bbase += (long long)32 * ldb;
    };
    auto stsA = [&](int buf) {
        uint32_t* Ah = smem + buf * 8192;
        uint32_t* Al = Ah + 2048;
        #pragma unroll
        for (int i = 0; i < 8; i++) {
            const float4 v = arg[i];
            const uint32_t h0 = bfpack(v.x, v.y);
            const uint32_t l0 = bfpack(v.x - bflowf(h0), v.y - bfhighf(h0));
            const uint32_t h1 = bfpack(v.z, v.w);
            const uint32_t l1 = bfpack(v.z - bflowf(h1), v.w - bfhighf(h1));
            Ah[i * 128 + aC[0]] = h0; Al[i * 128 + aC[0]] = l0;
            Ah[i * 128 + aC[1]] = h1; Al[i * 128 + aC[1]] = l1;
        }
    };
    auto stsB = [&](int buf) {
        uint32_t* Bh = smem + buf * 8192 + 4096;
        uint32_t* Bl = Bh + 2048;
        #pragma unroll
        for (int i = 0; i < 8; i++) {
            const uint32_t h0 = bfpack(brg[i][0], brg[i][1]);
            const uint32_t l0 = bfpack(brg[i][0] - bflowf(h0), brg[i][1] - bfhighf(h0));
            const uint32_t h1 = bfpack(brg[i][2], brg[i][3]);
            const uint32_t l1 = bfpack(brg[i][2] - bflowf(h1), brg[i][3] - bfhighf(h1));
            *(uint2*)(Bh + bOff[i]) = make_uint2(h0, h1);
            *(uint2*)(Bl + bOff[i]) = make_uint2(l0, l1);
        }
    };
    auto compute_chunk = [&](int buf, int kk) {
        uint32_t* Sb = smem + buf * 8192;
        const int laneA = lane ^ kk;
        const int laneB = lane ^ (((lane >> 4) & 1) << 2);
        #pragma unroll
        for (int half = 0; half < 2; half++) {
            uint2 bh[4], bl[4];
            #pragma unroll
            for (int j = 0; j < 4; j++) {
                const int idx = ((kk * 16 + ntb + half * 4 + j) * 32 + laneB) * 2;
                bh[j] = *(const uint2*)(Sb + 4096 + idx);
                bl[j] = *(const uint2*)(Sb + 6144 + idx);
            }
            #pragma unroll
            for (int mi = 0; mi < 4; mi++) {
                const int ai = ((kk * 8 + mtb + mi) * 32 + laneA) * 4;
                const uint4 ah = *(const uint4*)(Sb + ai);
                const uint4 al = *(const uint4*)(Sb + 2048 + ai);
                #pragma unroll
                for (int j = 0; j < 4; j++) {
                    float* c = acc[mi][half * 4 + j];
                    mma_bf(c, ah, bh[j]);
                    mma_bf(c, ah, bl[j]);
                    mma_bf(c, al, bh[j]);
                }
            }
        }
    };

    // prologue
    ldgA(); stsA(0); ldgB(); stsB(0);
    __syncthreads();

    for (int s = 0; s < S; s++) {
        const int b = s & 1;
        if (s + 1 < S) ldgA();
        compute_chunk(b, 0);
        if (s + 1 < S) { stsA(b ^ 1); ldgB(); }
        compute_chunk(b, 1);
        if (s + 1 < S) { stsB(b ^ 1); __syncthreads(); }
    }

    // ---- epilogue ----
    const int rbase = m0 + (wid >> 1) * 64 + (lane >> 2);
    const int cbase = n0 + (wid & 1) * 64 + 2 * (lane & 3);
    #pragma unroll
    for (int mi = 0; mi < 4; mi++) {
        #pragma unroll
        for (int h2 = 0; h2 < 2; h2++) {
            const int m = rbase + mi * 16 + h2 * 8;
            if (m >= Mloc) continue;
            float* crow = C + (long long)m * ldc;
            const float* rrow = (MODE == M_BIAS_RESID) ? (resid + (long long)m * ldc) : nullptr;
            #pragma unroll
            for (int nj = 0; nj < 8; nj++) {
                const int n = cbase + nj * 8;
                float v0 = acc[mi][nj][h2 * 2 + 0] + bias[n];
                float v1 = acc[mi][nj][h2 * 2 + 1] + bias[n + 1];
                if (MODE == M_GATHER_RELU) { v0 = fmaxf(v0, 0.f); v1 = fmaxf(v1, 0.f); }
                if (MODE == M_BIAS_RESID) { v0 += rrow[n]; v1 += rrow[n + 1]; }
                float2 vv; vv.x = v0; vv.y = v1;
                *(float2*)(crow + n) = vv;
            }
        }
    }
}

// ---------------- kv_sum: kv[b,d] = sum_t K[b,t,d]*V[b,t,d] ----------------
#define TSPLIT 8
__global__ void kvsum_part_kernel(const float* __restrict__ K,
                                  const float* __restrict__ V,
                                  float* __restrict__ part)
{
    const int b = blockIdx.y, ts = blockIdx.z;
    const int d = blockIdx.x * 128 + threadIdx.x;
    const long long base = ((long long)b * TT + (long long)ts * (TT / TSPLIT)) * DD;
    const float* Kp = K + base;
    const float* Vp = V + base;
    float acc = 0.f;
    #pragma unroll 4
    for (int t = 0; t < TT / TSPLIT; t++)
        acc += Kp[(long long)t * DD + d] * Vp[(long long)t * DD + d];
    part[((long long)ts * BBATCH + b) * DD + d] = acc;
}
__global__ void kvsum_reduce_kernel(const float* __restrict__ part, float* __restrict__ kv)
{
    const int i = blockIdx.x * blockDim.x + threadIdx.x;
    float a = 0.f;
    #pragma unroll
    for (int ts = 0; ts < TSPLIT; ts++) a += part[(long long)ts * BBATCH * DD + i];
    kv[i] = a;
}

// ---------------- LayerNorm (warp/token) ----------------
__global__ void ln1_kernel(const float* __restrict__ a,
                           const float* __restrict__ g, const float* __restrict__ beta,
                           float* __restrict__ out)
{
    const int t = (blockIdx.x * blockDim.x + threadIdx.x) >> 5;
    const int lane = threadIdx.x & 31;
    if (t >= BTOK) return;
    const float* ar = a + (long long)t * DD;
    float v[16], sum = 0.f, sq = 0.f;
    #pragma unroll
    for (int i = 0; i < 16; i++) {
        const float x = ar[i * 32 + lane];
        v[i] = x; sum += x; sq += x * x;
    }
    #pragma unroll
    for (int o = 16; o; o >>= 1) {
        sum += __shfl_xor_sync(0xffffffffu, sum, o);
        sq  += __shfl_xor_sync(0xffffffffu, sq, o);
    }
    const float mu = sum * (1.f / DD);
    const float rs = rsqrtf(sq * (1.f / DD) - mu * mu + EPSV);
    float* orow = out + (long long)t * DD;
    #pragma unroll
    for (int i = 0; i < 16; i++) {
        const int d = i * 32 + lane;
        orow[d] = (v[i] - mu) * rs * g[d] + beta[d];
    }
}

// final LN: out = LN(x1 + w0*y[off0] + w1*y[off1])
__global__ void ln2_moe_kernel(const float* __restrict__ x1, const float* __restrict__ y,
                               const int* __restrict__ goff, const float* __restrict__ gw,
                               const float* __restrict__ g, const float* __restrict__ beta,
                               float* __restrict__ out)
{
    const int t = (blockIdx.x * blockDim.x + threadIdx.x) >> 5;
    const int lane = threadIdx.x & 31;
    if (t >= BTOK) return;
    const float* ar = x1 + (long long)t * DD;
    const float* y0 = y + (long long)goff[2 * t] * DD;
    const float* y1 = y + (long long)goff[2 * t + 1] * DD;
    const float w0 = gw[2 * t], w1 = gw[2 * t + 1];
    float v[16], sum = 0.f, sq = 0.f;
    #pragma unroll
    for (int i = 0; i < 16; i++) {
        const int d = i * 32 + lane;
        const float x = ar[d] + w0 * y0[d] + w1 * y1[d];
        v[i] = x; sum += x; sq += x * x;
    }
    #pragma unroll
    for (int o = 16; o; o >>= 1) {
        sum += __shfl_xor_sync(0xffffffffu, sum, o);
        sq  += __shfl_xor_sync(0xffffffffu, sq, o);
    }
    const float mu = sum * (1.f / DD);
    const float rs = rsqrtf(sq * (1.f / DD) - mu * mu + EPSV);
    float* orow = out + (long long)t * DD;
    #pragma unroll
    for (int i = 0; i < 16; i++) {
        const int d = i * 32 + lane;
        orow[d] = (v[i] - mu) * rs * g[d] + beta[d];
    }
}

// ---------------- gating: softmax(E=4), top-2, route ----------------
__global__ void gating_kernel(const float* __restrict__ x1,
                              const float* __restrict__ Wg,
                              const float* __restrict__ bg)
{
    const int t = (blockIdx.x * blockDim.x + threadIdx.x) >> 5;
    const int lane = threadIdx.x & 31;
    if (t >= BTOK) return;
    const float* xr = x1 + (long long)t * DD;
    float s0 = 0.f, s1 = 0.f, s2 = 0.f, s3 = 0.f;
    for (int d = lane; d < DD; d += 32) {
        const float xv = xr[d];
        const float* w = Wg + d * EE;
        s0 += xv * w[0]; s1 += xv * w[1]; s2 += xv * w[2]; s3 += xv * w[3];
    }
    #pragma unroll
    for (int o = 16; o; o >>= 1) {
        s0 += __shfl_xor_sync(0xffffffffu, s0, o);
        s1 += __shfl_xor_sync(0xffffffffu, s1, o);
        s2 += __shfl_xor_sync(0xffffffffu, s2, o);
        s3 += __shfl_xor_sync(0xffffffffu, s3, o);
    }
    if (lane == 0) {
        float s[EE] = { s0 + bg[0], s1 + bg[1], s2 + bg[2], s3 + bg[3] };
        const float mx = fmaxf(fmaxf(s[0], s[1]), fmaxf(s[2], s[3]));
        float ex[EE], sm = 0.f;
        #pragma unroll
        for (int e = 0; e < EE; e++) { ex[e] = expf(s[e] - mx); sm += ex[e]; }
        float p[EE];
        #pragma unroll
        for (int e = 0; e < EE; e++) p[e] = ex[e] / sm;
        int i0 = 0;
        #pragma unroll
        for (int e = 1; e < EE; e++) if (p[e] > p[i0]) i0 = e;
        int i1 = -1;
        #pragma unroll
        for (int e = 0; e < EE; e++) {
            if (e == i0) continue;
            if (i1 < 0 || p[e] > p[i1]) i1 = e;
        }
        const int pos0 = atomicAdd(&d_cnt[i0], 1);
        d_tok[i0 * BTOK + pos0] = t;
        d_goff[2 * t] = i0 * BTOK + pos0;
        d_gw[2 * t] = p[i0];
        const int pos1 = atomicAdd(&d_cnt[i1], 1);
        d_tok[i1 * BTOK + pos1] = t;
        d_goff[2 * t + 1] = i1 * BTOK + pos1;
        d_gw[2 * t + 1] = p[i1];
    }
}

__global__ void zero_cnt_kernel()
{
    if (threadIdx.x < EE) d_cnt[threadIdx.x] = 0;
}

// ---------------- launch ----------------
extern "C" void kernel_launch(void* const* d_in, const int* in_sizes, int n_in,
                              void* d_out, int out_size)
{
    const float* x   = (const float*)d_in[0];
    const float* fb  = (const float*)d_in[1];
    const float* Wk  = (const float*)d_in[2];
    const float* bk  = (const float*)d_in[3];
    const float* Wv  = (const float*)d_in[4];
    const float* bvv = (const float*)d_in[5];
    const float* Wo  = (const float*)d_in[6];
    const float* bo  = (const float*)d_in[7];
    const float* g1  = (const float*)d_in[8];
    const float* be1 = (const float*)d_in[9];
    const float* Wg  = (const float*)d_in[10];
    const float* bg  = (const float*)d_in[11];
    const float* W1  = (const float*)d_in[12];
    const float* b1  = (const float*)d_in[13];
    const float* W2  = (const float*)d_in[14];
    const float* b2  = (const float*)d_in[15];
    const float* g2  = (const float*)d_in[16];
    const float* be2 = (const float*)d_in[17];
    float* out = (float*)d_out;

    float *K_, *V_, *wv_, *pre1_, *x1_, *h_, *y_, *part_, *kv_, *gw_;
    int *cnt_, *tok_, *goff_;
    cudaGetSymbolAddress((void**)&K_,    d_K);
    cudaGetSymbolAddress((void**)&V_,    d_V);
    cudaGetSymbolAddress((void**)&wv_,   d_wv);
    cudaGetSymbolAddress((void**)&pre1_, d_pre1);
    cudaGetSymbolAddress((void**)&x1_,   d_x1);
    cudaGetSymbolAddress((void**)&h_,    d_h);
    cudaGetSymbolAddress((void**)&y_,    d_y);
    cudaGetSymbolAddress((void**)&part_, d_kvpart);
    cudaGetSymbolAddress((void**)&kv_,   d_kv);
    cudaGetSymbolAddress((void**)&cnt_,  d_cnt);
    cudaGetSymbolAddress((void**)&tok_,  d_tok);
    cudaGetSymbolAddress((void**)&goff_, d_goff);
    cudaGetSymbolAddress((void**)&gw_,   d_gw);

    cudaFuncSetAttribute(tc_gemm<M_BIAS>,        cudaFuncAttributeMaxDynamicSharedMemorySize, SMEM_SZ);
    cudaFuncSetAttribute(tc_gemm<M_BIAS_RESID>,  cudaFuncAttributeMaxDynamicSharedMemorySize, SMEM_SZ);
    cudaFuncSetAttribute(tc_gemm<M_GATHER_RELU>, cudaFuncAttributeMaxDynamicSharedMemorySize, SMEM_SZ);
    cudaFuncSetAttribute(tc_gemm<M_DYN>,         cudaFuncAttributeMaxDynamicSharedMemorySize, SMEM_SZ);

    zero_cnt_kernel<<<1, 32>>>();

    // K = x @ Wk + bk ; V = x @ Wv + bv
    tc_gemm<M_BIAS><<<dim3(DD/128, BTOK/128, 1), 128, SMEM_SZ>>>(
        x, 0, Wk, DD, 0, K_, DD, 0, bk, 0, nullptr, BTOK, DD, nullptr, nullptr);
    tc_gemm<M_BIAS><<<dim3(DD/128, BTOK/128, 1), 128, SMEM_SZ>>>(
        x, 0, Wv, DD, 0, V_, DD, 0, bvv, 0, nullptr, BTOK, DD, nullptr, nullptr);

    // kv[b,d] = sum_t K*V
    kvsum_part_kernel<<<dim3(DD/128, BBATCH, TSPLIT), 128>>>(K_, V_, part_);
    kvsum_reduce_kernel<<<dim3((BBATCH*DD)/256), 256>>>(part_, kv_);

    // wv[b] = fb[b] @ V[b] + kv[b]
    tc_gemm<M_BIAS><<<dim3(DD/128, TT/128, BBATCH), 128, SMEM_SZ>>>(
        fb, (long long)TT*TT, V_, DD, (long long)TT*DD, wv_, DD, (long long)TT*DD,
        kv_, DD, nullptr, TT, TT, nullptr, nullptr);

    // pre1 = x + wv @ Wo + bo
    tc_gemm<M_BIAS_RESID><<<dim3(DD/128, BTOK/128, 1), 128, SMEM_SZ>>>(
        wv_, 0, Wo, DD, 0, pre1_, DD, 0, bo, 0, x, BTOK, DD, nullptr, nullptr);

    // x1 = LN(pre1)
    ln1_kernel<<<BTOK/8, 256>>>(pre1_, g1, be1, x1_);

    // gating + routing
    gating_kernel<<<BTOK/8, 256>>>(x1_, Wg, bg);

    // MoE experts, all 4 batched on z:
    // h[e] = relu(gather(x1) @ W1[e] + b1[e])
    tc_gemm<M_GATHER_RELU><<<dim3(FFD/128, BTOK/128, EE), 128, SMEM_SZ>>>(
        x1_, 0, W1, FFD, (long long)DD*FFD, h_, FFD, (long long)BTOK*FFD,
        b1, FFD, nullptr, 0, DD, cnt_, tok_);
    // y[e] = h[e] @ W2[e] + b2[e]
    tc_gemm<M_DYN><<<dim3(DD/128, BTOK/128, EE), 128, SMEM_SZ>>>(
        h_, (long long)BTOK*FFD, W2, DD, (long long)FFD*DD, y_, DD, (long long)BTOK*DD,
        b2, DD, nullptr, 0, FFD, cnt_, nullptr);

    // out = LN(x1 + w0*y[off0] + w1*y[off1])
    ln2_moe_kernel<<<BTOK/8, 256>>>(x1_, y_, goff_, gw_, g2, be2, out);
}